// round 10
// baseline (speedup 1.0000x reference)
#include <cuda_runtime.h>
#include <cstdint>
#include <cmath>

#define N_LEVELS 16
#define HASHMAP_SIZE 32768u
#define HASH_MASK 32767u
#define P1 2654435761u
#define P2 805459861u
#define MAXN 524288
#define BINS 262144          // 64^3 Morton bins over the occupied octant
#define SCAN_BLOCKS 256      // BINS / 1024
#define MAT_BLOCKS 2048      // 16*32768 / 256

// 4 MB materialized per-level tables (LoRA A@B), device-global scratch (no alloc).
__device__ float2 g_tables[N_LEVELS * HASHMAP_SIZE];
// Sort scratch
__device__ float4 g_xs4[MAXN];          // (x0, x1, x2, orig-as-bits)
__device__ int    g_hist[BINS];
__device__ int    g_off[BINS];
__device__ int    g_bsum[SCAN_BLOCKS];
__device__ int    g_bbase[SCAN_BLOCKS];

struct ResArr { float r[N_LEVELS]; };

// ---------------- Morton binning ----------------
__device__ __forceinline__ uint32_t part3_6(uint32_t v) {
    v &= 0x3Fu;
    v = (v | (v << 16)) & 0x030000FFu;
    v = (v | (v << 8))  & 0x0300F00Fu;
    v = (v | (v << 4))  & 0x030C30C3u;
    v = (v | (v << 2))  & 0x09249249u;
    return v;
}

// Morton bin over the occupied octant: xn in [0.5,1) -> c = floor((xn-0.5)*128) in [0,64)
__device__ __forceinline__ int bin_of(float X0, float X1, float X2) {
    float n0 = ((X0 + 1.0f) * 0.5f - 0.5f) * 128.0f;
    float n1 = ((X1 + 1.0f) * 0.5f - 0.5f) * 128.0f;
    float n2 = ((X2 + 1.0f) * 0.5f - 0.5f) * 128.0f;
    uint32_t c0 = (uint32_t)min(max((int)floorf(n0), 0), 63);
    uint32_t c1 = (uint32_t)min(max((int)floorf(n1), 0), 63);
    uint32_t c2 = (uint32_t)min(max((int)floorf(n2), 0), 63);
    return (int)((part3_6(c0) << 2) | (part3_6(c1) << 1) | part3_6(c2));
}

// ---------------- Fused: materialize tables + histogram ----------------
// Blocks [0, MAT_BLOCKS): tables = einsum('lsr,lrf->lsf') (one entry/thread).
// Blocks [MAT_BLOCKS, ...): histogram of point bins. Independent jobs, one launch.
__global__ void mat_hist_kernel(const float* __restrict__ tableA,
                                const float* __restrict__ tableB,
                                const float* __restrict__ x, int n) {
    int b = blockIdx.x;
    if (b < MAT_BLOCKS) {
        int t = b * 256 + threadIdx.x;            // [0, 16*32768)
        int l = t >> 15;
        float4 a = __ldg(((const float4*)tableA) + t);
        const float* Bl = tableB + l * 8;
        float b00 = __ldg(Bl + 0), b01 = __ldg(Bl + 1);
        float b10 = __ldg(Bl + 2), b11 = __ldg(Bl + 3);
        float b20 = __ldg(Bl + 4), b21 = __ldg(Bl + 5);
        float b30 = __ldg(Bl + 6), b31 = __ldg(Bl + 7);
        float f0 = a.x * b00 + a.y * b10 + a.z * b20 + a.w * b30;
        float f1 = a.x * b01 + a.y * b11 + a.z * b21 + a.w * b31;
        g_tables[t] = make_float2(f0, f1);
    } else {
        int i = (b - MAT_BLOCKS) * 256 + threadIdx.x;
        if (i >= n) return;
        int bi = bin_of(x[3 * i], x[3 * i + 1], x[3 * i + 2]);
        atomicAdd(&g_hist[bi], 1);
    }
}

// Pass A: SCAN_BLOCKS blocks x 1024 threads, one thread per bin (coalesced).
__global__ void scanA_kernel() {
    __shared__ int wsum[32];
    int b = blockIdx.x, t = threadIdx.x;
    int idx = (b << 10) + t;
    int v = g_hist[idx];
    int lane = t & 31, wid = t >> 5;
    int inc = v;
#pragma unroll
    for (int o = 1; o < 32; o <<= 1) {
        int s = __shfl_up_sync(0xffffffffu, inc, o);
        if (lane >= o) inc += s;
    }
    if (lane == 31) wsum[wid] = inc;
    __syncthreads();
    if (wid == 0) {
        int wv = wsum[lane];
#pragma unroll
        for (int o = 1; o < 32; o <<= 1) {
            int s = __shfl_up_sync(0xffffffffu, wv, o);
            if (lane >= o) wv += s;
        }
        wsum[lane] = wv;
    }
    __syncthreads();
    int excl = inc - v + (wid > 0 ? wsum[wid - 1] : 0);
    g_off[idx] = excl;
    if (t == 1023) g_bsum[b] = excl + v;
}

// Pass B: exclusive scan of SCAN_BLOCKS block sums (one block of 256).
__global__ void scanB_kernel() {
    __shared__ int wsum[8];
    int t = threadIdx.x;
    int lane = t & 31, wid = t >> 5;
    int v = g_bsum[t];
    int inc = v;
#pragma unroll
    for (int o = 1; o < 32; o <<= 1) {
        int s = __shfl_up_sync(0xffffffffu, inc, o);
        if (lane >= o) inc += s;
    }
    if (lane == 31) wsum[wid] = inc;
    __syncthreads();
    if (wid == 0 && lane < 8) {
        int wv = wsum[lane];
#pragma unroll
        for (int o = 1; o < 8; o <<= 1) {
            int s = __shfl_up_sync(0xffu, wv, o);
            if (lane >= o) wv += s;
        }
        wsum[lane] = wv;
    }
    __syncthreads();
    g_bbase[t] = inc - v + (wid > 0 ? wsum[wid - 1] : 0);
}

__global__ void scatter_kernel(const float* __restrict__ x, int n) {
    int i = blockIdx.x * blockDim.x + threadIdx.x;
    if (i >= n) return;
    float X0 = x[3 * i], X1 = x[3 * i + 1], X2 = x[3 * i + 2];
    int b = bin_of(X0, X1, X2);
    int pos = g_bbase[b >> 10] + atomicAdd(&g_off[b], 1);
    g_xs4[pos] = make_float4(X0, X1, X2, __int_as_float(i));
}

// ---------------- Encode: unchanged from R9 winner ----------------
__global__ void __launch_bounds__(256)
encode_kernel(const float4* __restrict__ xs4, float* __restrict__ out, int n, ResArr res) {
    __shared__ float4 so[32 * 9];   // [point][warp], padded stride 9
    __shared__ int sorig[32];

    int w = threadIdx.x >> 5;       // level-pair (levels 2w, 2w+1)
    int j = threadIdx.x & 31;       // point lane
    int pb = blockIdx.x * 32;
    int i = pb + j;

    float4 a4 = make_float4(0.f, 0.f, 0.f, 0.f);

    if (i < n) {
        float4 xq = __ldg(xs4 + i);
        if (w == 0) sorig[j] = __float_as_int(xq.w);
        float x0 = (xq.x + 1.0f) * 0.5f;
        float x1 = (xq.y + 1.0f) * 0.5f;
        float x2 = (xq.z + 1.0f) * 0.5f;

        float acc[4];

#pragma unroll
        for (int u = 0; u < 2; u++) {
            int l = 2 * w + u;      // warp-uniform
            float r = res.r[l];
            float xl0 = x0 * r, xl1 = x1 * r, xl2 = x2 * r;
            float f0 = floorf(xl0), f1 = floorf(xl1), f2 = floorf(xl2);
            float w0 = xl0 - f0, w1 = xl1 - f1, w2 = xl2 - f2;
            float v0 = 1.0f - w0, v1 = 1.0f - w1, v2 = 1.0f - w2;
            uint32_t i0 = (uint32_t)f0;
            uint32_t i1 = (uint32_t)f1;
            uint32_t i2 = (uint32_t)f2;

            uint32_t h1a = i1 * P1;          uint32_t h1b = h1a + P1;
            uint32_t h2a = i2 * P2;          uint32_t h2b = h2a + P2;
            uint32_t i0b = i0 + 1u;
            bool odd = (i0 & 1u) != 0u;

            const float2* __restrict__ tl  = g_tables + (l << 15);
            const float4* __restrict__ tl4 = (const float4*)tl;

            uint32_t idx0 = (i0  ^ h1a ^ h2a) & HASH_MASK;
            uint32_t idx1 = (i0b ^ h1a ^ h2a) & HASH_MASK;
            uint32_t idx2 = (i0  ^ h1b ^ h2a) & HASH_MASK;
            uint32_t idx3 = (i0b ^ h1b ^ h2a) & HASH_MASK;
            uint32_t idx4 = (i0  ^ h1a ^ h2b) & HASH_MASK;
            uint32_t idx5 = (i0b ^ h1a ^ h2b) & HASH_MASK;
            uint32_t idx6 = (i0  ^ h1b ^ h2b) & HASH_MASK;
            uint32_t idx7 = (i0b ^ h1b ^ h2b) & HASH_MASK;

            float4 q0 = __ldg(tl4 + (idx0 >> 1));
            float4 q2 = __ldg(tl4 + (idx2 >> 1));
            float4 q4 = __ldg(tl4 + (idx4 >> 1));
            float4 q6 = __ldg(tl4 + (idx6 >> 1));

            float2 s1 = make_float2(0.f, 0.f), s3 = s1, s5 = s1, s7 = s1;
            if (odd) {
                s1 = __ldg(tl + idx1);
                s3 = __ldg(tl + idx3);
                s5 = __ldg(tl + idx5);
                s7 = __ldg(tl + idx7);
            }

            bool hi0 = (idx0 & 1u) != 0u;
            bool hi2 = (idx2 & 1u) != 0u;
            bool hi4 = (idx4 & 1u) != 0u;
            bool hi6 = (idx6 & 1u) != 0u;

            float2 t0 = hi0 ? make_float2(q0.z, q0.w) : make_float2(q0.x, q0.y);
            float2 t2 = hi2 ? make_float2(q2.z, q2.w) : make_float2(q2.x, q2.y);
            float2 t4 = hi4 ? make_float2(q4.z, q4.w) : make_float2(q4.x, q4.y);
            float2 t6 = hi6 ? make_float2(q6.z, q6.w) : make_float2(q6.x, q6.y);

            float2 t1 = odd ? s1 : (hi0 ? make_float2(q0.x, q0.y) : make_float2(q0.z, q0.w));
            float2 t3 = odd ? s3 : (hi2 ? make_float2(q2.x, q2.y) : make_float2(q2.z, q2.w));
            float2 t5 = odd ? s5 : (hi4 ? make_float2(q4.x, q4.y) : make_float2(q4.z, q4.w));
            float2 t7 = odd ? s7 : (hi6 ? make_float2(q6.x, q6.y) : make_float2(q6.z, q6.w));

            float wc0 = v0 * v1 * v2;
            float wc1 = w0 * v1 * v2;
            float wc2 = v0 * w1 * v2;
            float wc3 = w0 * w1 * v2;
            float wc4 = v0 * v1 * w2;
            float wc5 = w0 * v1 * w2;
            float wc6 = v0 * w1 * w2;
            float wc7 = w0 * w1 * w2;

            float a0 = t0.x * wc0, a1 = t0.y * wc0;
            a0 = fmaf(t1.x, wc1, a0); a1 = fmaf(t1.y, wc1, a1);
            a0 = fmaf(t2.x, wc2, a0); a1 = fmaf(t2.y, wc2, a1);
            a0 = fmaf(t3.x, wc3, a0); a1 = fmaf(t3.y, wc3, a1);
            a0 = fmaf(t4.x, wc4, a0); a1 = fmaf(t4.y, wc4, a1);
            a0 = fmaf(t5.x, wc5, a0); a1 = fmaf(t5.y, wc5, a1);
            a0 = fmaf(t6.x, wc6, a0); a1 = fmaf(t6.y, wc6, a1);
            a0 = fmaf(t7.x, wc7, a0); a1 = fmaf(t7.y, wc7, a1);

            acc[2 * u + 0] = a0;
            acc[2 * u + 1] = a1;
        }
        a4 = make_float4(acc[0], acc[1], acc[2], acc[3]);
    }

    so[j * 9 + w] = a4;
    __syncthreads();

    int r = threadIdx.x >> 3;
    int c = threadIdx.x & 7;
    int ir = pb + r;
    if (ir < n) {
        int o = sorig[r];
        ((float4*)(out + (size_t)o * (2 * N_LEVELS)))[c] = so[r * 9 + c];
    }
}

extern "C" void kernel_launch(void* const* d_in, const int* in_sizes, int n_in,
                              void* d_out, int out_size) {
    const float* x       = (const float*)d_in[0];   // [N, 3]
    const float* tableA  = (const float*)d_in[1];   // [16, 32768, 4]
    const float* tableB  = (const float*)d_in[2];   // [16, 4, 2]
    float* out           = (float*)d_out;           // [N, 32]
    int n = in_sizes[0] / 3;
    if (n > MAXN) n = MAXN;   // scratch capacity (dataset is 524288)

    ResArr res;
    {
        double b = exp((log(512.0) - log(16.0)) / (double)(N_LEVELS - 1));
        for (int l = 0; l < N_LEVELS; l++)
            res.r[l] = (float)floor(16.0 * pow(b, (double)l));
    }

    // Zero histogram via graph memset node (cheaper than a kernel).
    void* hist_ptr = nullptr;
    cudaGetSymbolAddress(&hist_ptr, g_hist);
    cudaMemsetAsync(hist_ptr, 0, BINS * sizeof(int), 0);

    // Fused materialize + histogram (independent halves of one grid).
    int hist_blocks = (n + 255) / 256;
    mat_hist_kernel<<<MAT_BLOCKS + hist_blocks, 256>>>(tableA, tableB, x, n);

    scanA_kernel<<<SCAN_BLOCKS, 1024>>>();
    scanB_kernel<<<1, 256>>>();
    scatter_kernel<<<(n + 255) / 256, 256>>>(x, n);

    float4* xs_ptr = nullptr;
    cudaGetSymbolAddress((void**)&xs_ptr, g_xs4);
    encode_kernel<<<(n + 31) / 32, 256>>>(xs_ptr, out, n, res);
}

// round 11
// speedup vs baseline: 1.3865x; 1.3865x over previous
#include <cuda_runtime.h>
#include <cstdint>
#include <cmath>

#define N_LEVELS 16
#define HASHMAP_SIZE 32768u
#define HASH_MASK 32767u
#define P1 2654435761u
#define P2 805459861u
#define MAXN 524288
#define BINS 32768           // 32^3 Morton bins over the occupied octant
#define SCAN_BLOCKS 32       // BINS / 1024

// 4 MB materialized per-level tables (LoRA A@B), device-global scratch (no alloc).
__device__ float2 g_tables[N_LEVELS * HASHMAP_SIZE];
// Sort scratch
__device__ float4 g_xs4[MAXN];          // (x0, x1, x2, orig-as-bits)
__device__ int    g_hist[BINS];
__device__ int    g_off[BINS];
__device__ int    g_bsum[SCAN_BLOCKS];
__device__ int    g_bbase[SCAN_BLOCKS];
__device__ int    g_done;               // scanAB completion ticket (self-resetting)

struct ResArr { float r[N_LEVELS]; };

// ---------------- Kernel 1: materialize tables = einsum('lsr,lrf->lsf') ----------------
__global__ void materialize_kernel(const float* __restrict__ tableA,
                                   const float* __restrict__ tableB) {
    int t = blockIdx.x * blockDim.x + threadIdx.x;
    if (t >= N_LEVELS * (int)HASHMAP_SIZE) return;
    int l = t >> 15;
    float4 a = __ldg(((const float4*)tableA) + t);
    const float* Bl = tableB + l * 8;
    float b00 = __ldg(Bl + 0), b01 = __ldg(Bl + 1);
    float b10 = __ldg(Bl + 2), b11 = __ldg(Bl + 3);
    float b20 = __ldg(Bl + 4), b21 = __ldg(Bl + 5);
    float b30 = __ldg(Bl + 6), b31 = __ldg(Bl + 7);
    float f0 = a.x * b00 + a.y * b10 + a.z * b20 + a.w * b30;
    float f1 = a.x * b01 + a.y * b11 + a.z * b21 + a.w * b31;
    g_tables[t] = make_float2(f0, f1);
}

// ---------------- Morton binning (32^3 over occupied octant) ----------------
__device__ __forceinline__ uint32_t part3_6(uint32_t v) {
    v &= 0x3Fu;
    v = (v | (v << 16)) & 0x030000FFu;
    v = (v | (v << 8))  & 0x0300F00Fu;
    v = (v | (v << 4))  & 0x030C30C3u;
    v = (v | (v << 2))  & 0x09249249u;
    return v;
}

// xn in [0.5,1) -> c = floor((xn-0.5)*64) in [0,32); Morton interleave (15 bits).
__device__ __forceinline__ int bin_of(float X0, float X1, float X2) {
    float n0 = ((X0 + 1.0f) * 0.5f - 0.5f) * 64.0f;
    float n1 = ((X1 + 1.0f) * 0.5f - 0.5f) * 64.0f;
    float n2 = ((X2 + 1.0f) * 0.5f - 0.5f) * 64.0f;
    uint32_t c0 = (uint32_t)min(max((int)floorf(n0), 0), 31);
    uint32_t c1 = (uint32_t)min(max((int)floorf(n1), 0), 31);
    uint32_t c2 = (uint32_t)min(max((int)floorf(n2), 0), 31);
    return (int)((part3_6(c0) << 2) | (part3_6(c1) << 1) | part3_6(c2));
}

__global__ void hist_kernel(const float* __restrict__ x, int n) {
    int i = blockIdx.x * blockDim.x + threadIdx.x;
    if (i >= n) return;
    int b = bin_of(x[3 * i], x[3 * i + 1], x[3 * i + 2]);
    atomicAdd(&g_hist[b], 1);
}

// Fused scan: 32 blocks x 1024 threads, one thread per bin (coalesced).
// Self-zeroes g_hist (so hist starts from zero on the next replay) and the
// LAST finishing block performs the 32-entry top-level exclusive scan.
__global__ void scanAB_kernel() {
    __shared__ int wsum[32];
    __shared__ int isLast;
    int b = blockIdx.x, t = threadIdx.x;
    int idx = (b << 10) + t;
    int v = g_hist[idx];
    g_hist[idx] = 0;                           // self-zero for next replay
    int lane = t & 31, wid = t >> 5;
    int inc = v;
#pragma unroll
    for (int o = 1; o < 32; o <<= 1) {
        int s = __shfl_up_sync(0xffffffffu, inc, o);
        if (lane >= o) inc += s;
    }
    if (lane == 31) wsum[wid] = inc;
    __syncthreads();
    if (wid == 0) {
        int wv = wsum[lane];
#pragma unroll
        for (int o = 1; o < 32; o <<= 1) {
            int s = __shfl_up_sync(0xffffffffu, wv, o);
            if (lane >= o) wv += s;
        }
        wsum[lane] = wv;
    }
    __syncthreads();
    int excl = inc - v + (wid > 0 ? wsum[wid - 1] : 0);
    g_off[idx] = excl;
    if (t == 1023) g_bsum[b] = excl + v;
    __threadfence();
    if (t == 0) {
        int ticket = atomicAdd(&g_done, 1);
        isLast = (ticket == SCAN_BLOCKS - 1) ? 1 : 0;
    }
    __syncthreads();
    if (isLast && wid == 0) {
        volatile int* vb = g_bsum;
        int sv = vb[lane];
        int si = sv;
#pragma unroll
        for (int o = 1; o < 32; o <<= 1) {
            int s = __shfl_up_sync(0xffffffffu, si, o);
            if (lane >= o) si += s;
        }
        g_bbase[lane] = si - sv;
        if (lane == 0) g_done = 0;             // reset ticket for next replay
        __threadfence();
    }
}

__global__ void scatter_kernel(const float* __restrict__ x, int n) {
    int i = blockIdx.x * blockDim.x + threadIdx.x;
    if (i >= n) return;
    float X0 = x[3 * i], X1 = x[3 * i + 1], X2 = x[3 * i + 2];
    int b = bin_of(X0, X1, X2);
    int pos = g_bbase[b >> 10] + atomicAdd(&g_off[b], 1);
    g_xs4[pos] = make_float4(X0, X1, X2, __int_as_float(i));
}

// ---------------- Kernel 2: hash-grid trilinear encode ----------------
// Block = 256 threads = 8 warps, 32 (Morton-sorted) points per block.
// Warp w handles levels w and 15-w (balanced: one cheap + one expensive level
// per warp). Level is warp-uniform; sorted points collapse gather addresses.
// Per-level float2 smem array -> coalesced float4 row stores.
__global__ void __launch_bounds__(256)
encode_kernel(const float4* __restrict__ xs4, float* __restrict__ out, int n, ResArr res) {
    __shared__ __align__(16) float2 sf[32 * 18];   // [point][level], stride 18
    __shared__ int sorig[32];

    int w = threadIdx.x >> 5;       // warp -> levels w, 15-w
    int j = threadIdx.x & 31;       // point lane
    int pb = blockIdx.x * 32;
    int i = pb + j;

    float2 accA = make_float2(0.f, 0.f), accB = accA;

    if (i < n) {
        float4 xq = __ldg(xs4 + i);
        if (w == 0) sorig[j] = __float_as_int(xq.w);
        float x0 = (xq.x + 1.0f) * 0.5f;
        float x1 = (xq.y + 1.0f) * 0.5f;
        float x2 = (xq.z + 1.0f) * 0.5f;

#pragma unroll
        for (int u = 0; u < 2; u++) {
            int l = u ? (15 - w) : w;   // warp-uniform
            float r = res.r[l];
            float xl0 = x0 * r, xl1 = x1 * r, xl2 = x2 * r;
            float f0 = floorf(xl0), f1 = floorf(xl1), f2 = floorf(xl2);
            float w0 = xl0 - f0, w1 = xl1 - f1, w2 = xl2 - f2;
            float v0 = 1.0f - w0, v1 = 1.0f - w1, v2 = 1.0f - w2;
            uint32_t i0 = (uint32_t)f0;
            uint32_t i1 = (uint32_t)f1;
            uint32_t i2 = (uint32_t)f2;

            uint32_t h1a = i1 * P1;          uint32_t h1b = h1a + P1;
            uint32_t h2a = i2 * P2;          uint32_t h2b = h2a + P2;
            uint32_t i0b = i0 + 1u;
            bool odd = (i0 & 1u) != 0u;

            const float2* __restrict__ tl  = g_tables + (l << 15);
            const float4* __restrict__ tl4 = (const float4*)tl;

            uint32_t idx0 = (i0  ^ h1a ^ h2a) & HASH_MASK;
            uint32_t idx1 = (i0b ^ h1a ^ h2a) & HASH_MASK;
            uint32_t idx2 = (i0  ^ h1b ^ h2a) & HASH_MASK;
            uint32_t idx3 = (i0b ^ h1b ^ h2a) & HASH_MASK;
            uint32_t idx4 = (i0  ^ h1a ^ h2b) & HASH_MASK;
            uint32_t idx5 = (i0b ^ h1a ^ h2b) & HASH_MASK;
            uint32_t idx6 = (i0  ^ h1b ^ h2b) & HASH_MASK;
            uint32_t idx7 = (i0b ^ h1b ^ h2b) & HASH_MASK;

            float4 q0 = __ldg(tl4 + (idx0 >> 1));
            float4 q2 = __ldg(tl4 + (idx2 >> 1));
            float4 q4 = __ldg(tl4 + (idx4 >> 1));
            float4 q6 = __ldg(tl4 + (idx6 >> 1));

            float2 s1 = make_float2(0.f, 0.f), s3 = s1, s5 = s1, s7 = s1;
            if (odd) {
                s1 = __ldg(tl + idx1);
                s3 = __ldg(tl + idx3);
                s5 = __ldg(tl + idx5);
                s7 = __ldg(tl + idx7);
            }

            bool hi0 = (idx0 & 1u) != 0u;
            bool hi2 = (idx2 & 1u) != 0u;
            bool hi4 = (idx4 & 1u) != 0u;
            bool hi6 = (idx6 & 1u) != 0u;

            float2 t0 = hi0 ? make_float2(q0.z, q0.w) : make_float2(q0.x, q0.y);
            float2 t2 = hi2 ? make_float2(q2.z, q2.w) : make_float2(q2.x, q2.y);
            float2 t4 = hi4 ? make_float2(q4.z, q4.w) : make_float2(q4.x, q4.y);
            float2 t6 = hi6 ? make_float2(q6.z, q6.w) : make_float2(q6.x, q6.y);

            float2 t1 = odd ? s1 : (hi0 ? make_float2(q0.x, q0.y) : make_float2(q0.z, q0.w));
            float2 t3 = odd ? s3 : (hi2 ? make_float2(q2.x, q2.y) : make_float2(q2.z, q2.w));
            float2 t5 = odd ? s5 : (hi4 ? make_float2(q4.x, q4.y) : make_float2(q4.z, q4.w));
            float2 t7 = odd ? s7 : (hi6 ? make_float2(q6.x, q6.y) : make_float2(q6.z, q6.w));

            float wc0 = v0 * v1 * v2;
            float wc1 = w0 * v1 * v2;
            float wc2 = v0 * w1 * v2;
            float wc3 = w0 * w1 * v2;
            float wc4 = v0 * v1 * w2;
            float wc5 = w0 * v1 * w2;
            float wc6 = v0 * w1 * w2;
            float wc7 = w0 * w1 * w2;

            float a0 = t0.x * wc0, a1 = t0.y * wc0;
            a0 = fmaf(t1.x, wc1, a0); a1 = fmaf(t1.y, wc1, a1);
            a0 = fmaf(t2.x, wc2, a0); a1 = fmaf(t2.y, wc2, a1);
            a0 = fmaf(t3.x, wc3, a0); a1 = fmaf(t3.y, wc3, a1);
            a0 = fmaf(t4.x, wc4, a0); a1 = fmaf(t4.y, wc4, a1);
            a0 = fmaf(t5.x, wc5, a0); a1 = fmaf(t5.y, wc5, a1);
            a0 = fmaf(t6.x, wc6, a0); a1 = fmaf(t6.y, wc6, a1);
            a0 = fmaf(t7.x, wc7, a0); a1 = fmaf(t7.y, wc7, a1);

            if (u == 0) accA = make_float2(a0, a1);
            else        accB = make_float2(a0, a1);
        }
    }

    sf[j * 18 + w]        = accA;   // level w
    sf[j * 18 + (15 - w)] = accB;   // level 15-w
    __syncthreads();

    // Store phase: thread t writes chunk c (levels 2c, 2c+1) of row r.
    int r = threadIdx.x >> 3;
    int c = threadIdx.x & 7;
    int ir = pb + r;
    if (ir < n) {
        int o = sorig[r];
        float4 v = *(const float4*)&sf[r * 18 + 2 * c];
        ((float4*)(out + (size_t)o * (2 * N_LEVELS)))[c] = v;
    }
}

extern "C" void kernel_launch(void* const* d_in, const int* in_sizes, int n_in,
                              void* d_out, int out_size) {
    const float* x       = (const float*)d_in[0];   // [N, 3]
    const float* tableA  = (const float*)d_in[1];   // [16, 32768, 4]
    const float* tableB  = (const float*)d_in[2];   // [16, 4, 2]
    float* out           = (float*)d_out;           // [N, 32]
    int n = in_sizes[0] / 3;
    if (n > MAXN) n = MAXN;   // scratch capacity (dataset is 524288)

    ResArr res;
    {
        double b = exp((log(512.0) - log(16.0)) / (double)(N_LEVELS - 1));
        for (int l = 0; l < N_LEVELS; l++)
            res.r[l] = (float)floor(16.0 * pow(b, (double)l));
    }

    int tab_entries = N_LEVELS * (int)HASHMAP_SIZE;
    materialize_kernel<<<(tab_entries + 255) / 256, 256>>>(tableA, tableB);

    // Spatial counting sort: hist -> fused scan (self-zeroing) -> scatter.
    hist_kernel<<<(n + 255) / 256, 256>>>(x, n);
    scanAB_kernel<<<SCAN_BLOCKS, 1024>>>();
    scatter_kernel<<<(n + 255) / 256, 256>>>(x, n);

    float4* xs_ptr = nullptr;
    cudaGetSymbolAddress((void**)&xs_ptr, g_xs4);
    encode_kernel<<<(n + 31) / 32, 256>>>(xs_ptr, out, n, res);
}

// round 15
// speedup vs baseline: 1.4525x; 1.0476x over previous
#include <cuda_runtime.h>
#include <cstdint>
#include <cmath>

#define N_LEVELS 16
#define HASHMAP_SIZE 32768u
#define HASH_MASK 32767u
#define P1 2654435761u
#define P2 805459861u
#define MAXN 524288
#define BINS 262144          // 64^3 Morton bins over the occupied octant
#define SCAN_BLOCKS 256      // BINS / 1024

// 4 MB materialized per-level tables (LoRA A@B), device-global scratch (no alloc).
__device__ float2 g_tables[N_LEVELS * HASHMAP_SIZE];
// Sort scratch
__device__ float4 g_xs4[MAXN];          // (x0, x1, x2, orig-as-bits)
__device__ int    g_hist[BINS];
__device__ int    g_off[BINS];
__device__ int    g_bsum[SCAN_BLOCKS];
__device__ int    g_bbase[SCAN_BLOCKS];
__device__ int    g_done;               // scan completion ticket (self-resetting)

struct ResArr { float r[N_LEVELS]; };

// ---------------- Kernel 1: materialize tables = einsum('lsr,lrf->lsf') ----------------
__global__ void materialize_kernel(const float* __restrict__ tableA,
                                   const float* __restrict__ tableB) {
    int t = blockIdx.x * blockDim.x + threadIdx.x;
    if (t >= N_LEVELS * (int)HASHMAP_SIZE) return;
    int l = t >> 15;
    float4 a = __ldg(((const float4*)tableA) + t);
    const float* Bl = tableB + l * 8;
    float b00 = __ldg(Bl + 0), b01 = __ldg(Bl + 1);
    float b10 = __ldg(Bl + 2), b11 = __ldg(Bl + 3);
    float b20 = __ldg(Bl + 4), b21 = __ldg(Bl + 5);
    float b30 = __ldg(Bl + 6), b31 = __ldg(Bl + 7);
    float f0 = a.x * b00 + a.y * b10 + a.z * b20 + a.w * b30;
    float f1 = a.x * b01 + a.y * b11 + a.z * b21 + a.w * b31;
    g_tables[t] = make_float2(f0, f1);
}

// ---------------- Morton binning (64^3 over occupied octant, as in R9) -------
__device__ __forceinline__ uint32_t part3_6(uint32_t v) {
    v &= 0x3Fu;
    v = (v | (v << 16)) & 0x030000FFu;
    v = (v | (v << 8))  & 0x0300F00Fu;
    v = (v | (v << 4))  & 0x030C30C3u;
    v = (v | (v << 2))  & 0x09249249u;
    return v;
}

// xn in [0.5,1) -> c = floor((xn-0.5)*128) in [0,64); Morton interleave.
__device__ __forceinline__ int bin_of(float X0, float X1, float X2) {
    float n0 = ((X0 + 1.0f) * 0.5f - 0.5f) * 128.0f;
    float n1 = ((X1 + 1.0f) * 0.5f - 0.5f) * 128.0f;
    float n2 = ((X2 + 1.0f) * 0.5f - 0.5f) * 128.0f;
    uint32_t c0 = (uint32_t)min(max((int)floorf(n0), 0), 63);
    uint32_t c1 = (uint32_t)min(max((int)floorf(n1), 0), 63);
    uint32_t c2 = (uint32_t)min(max((int)floorf(n2), 0), 63);
    return (int)((part3_6(c0) << 2) | (part3_6(c1) << 1) | part3_6(c2));
}

__global__ void hist_kernel(const float* __restrict__ x, int n) {
    int i = blockIdx.x * blockDim.x + threadIdx.x;
    if (i >= n) return;
    int b = bin_of(x[3 * i], x[3 * i + 1], x[3 * i + 2]);
    atomicAdd(&g_hist[b], 1);
}

// Fused scan: 256 blocks x 1024 threads, one thread per bin (coalesced).
// Self-zeroes g_hist for the next graph replay; last-finishing block does the
// 256-entry top-level exclusive scan with one warp (8 entries per lane).
__global__ void scanAB_kernel() {
    __shared__ int wsum[32];
    __shared__ int isLast;
    int b = blockIdx.x, t = threadIdx.x;
    int idx = (b << 10) + t;
    int v = g_hist[idx];
    g_hist[idx] = 0;                           // self-zero for next replay
    int lane = t & 31, wid = t >> 5;
    int inc = v;
#pragma unroll
    for (int o = 1; o < 32; o <<= 1) {
        int s = __shfl_up_sync(0xffffffffu, inc, o);
        if (lane >= o) inc += s;
    }
    if (lane == 31) wsum[wid] = inc;
    __syncthreads();
    if (wid == 0) {
        int wv = wsum[lane];
#pragma unroll
        for (int o = 1; o < 32; o <<= 1) {
            int s = __shfl_up_sync(0xffffffffu, wv, o);
            if (lane >= o) wv += s;
        }
        wsum[lane] = wv;
    }
    __syncthreads();
    int excl = inc - v + (wid > 0 ? wsum[wid - 1] : 0);
    g_off[idx] = excl;
    if (t == 1023) g_bsum[b] = excl + v;
    __threadfence();
    if (t == 0) {
        int ticket = atomicAdd(&g_done, 1);
        isLast = (ticket == SCAN_BLOCKS - 1) ? 1 : 0;
    }
    __syncthreads();
    if (isLast && wid == 0) {
        // one warp scans 256 block sums: lane owns entries [8*lane, 8*lane+8)
        volatile int* vb = g_bsum;
        int e[8], s = 0;
#pragma unroll
        for (int k = 0; k < 8; k++) { e[k] = vb[lane * 8 + k]; s += e[k]; }
        int si = s;
#pragma unroll
        for (int o = 1; o < 32; o <<= 1) {
            int sh = __shfl_up_sync(0xffffffffu, si, o);
            if (lane >= o) si += sh;
        }
        int run = si - s;                      // exclusive prefix of this lane's chunk
#pragma unroll
        for (int k = 0; k < 8; k++) { g_bbase[lane * 8 + k] = run; run += e[k]; }
        if (lane == 0) g_done = 0;             // reset ticket for next replay
        __threadfence();
    }
}

// Scatter: 2 points per thread (MLP=2 across the L2-atomic latency).
__global__ void scatter_kernel(const float* __restrict__ x, int n) {
    int base = (blockIdx.x * blockDim.x + threadIdx.x) * 2;
#pragma unroll
    for (int k = 0; k < 2; k++) {
        int i = base + k;
        if (i >= n) return;
        float X0 = x[3 * i], X1 = x[3 * i + 1], X2 = x[3 * i + 2];
        int b = bin_of(X0, X1, X2);
        int pos = g_bbase[b >> 10] + atomicAdd(&g_off[b], 1);
        g_xs4[pos] = make_float4(X0, X1, X2, __int_as_float(i));
    }
}

// ---------------- Kernel 2: hash-grid trilinear encode (R9 verbatim) ---------
__global__ void __launch_bounds__(256)
encode_kernel(const float4* __restrict__ xs4, float* __restrict__ out, int n, ResArr res) {
    __shared__ float4 so[32 * 9];   // [point][warp], padded stride 9
    __shared__ int sorig[32];

    int w = threadIdx.x >> 5;       // level-pair (levels 2w, 2w+1)
    int j = threadIdx.x & 31;       // point lane
    int pb = blockIdx.x * 32;
    int i = pb + j;

    float4 a4 = make_float4(0.f, 0.f, 0.f, 0.f);

    if (i < n) {
        float4 xq = __ldg(xs4 + i);
        if (w == 0) sorig[j] = __float_as_int(xq.w);
        float x0 = (xq.x + 1.0f) * 0.5f;
        float x1 = (xq.y + 1.0f) * 0.5f;
        float x2 = (xq.z + 1.0f) * 0.5f;

        float acc[4];

#pragma unroll
        for (int u = 0; u < 2; u++) {
            int l = 2 * w + u;      // warp-uniform
            float r = res.r[l];
            float xl0 = x0 * r, xl1 = x1 * r, xl2 = x2 * r;
            float f0 = floorf(xl0), f1 = floorf(xl1), f2 = floorf(xl2);
            float w0 = xl0 - f0, w1 = xl1 - f1, w2 = xl2 - f2;
            float v0 = 1.0f - w0, v1 = 1.0f - w1, v2 = 1.0f - w2;
            uint32_t i0 = (uint32_t)f0;
            uint32_t i1 = (uint32_t)f1;
            uint32_t i2 = (uint32_t)f2;

            uint32_t h1a = i1 * P1;          uint32_t h1b = h1a + P1;
            uint32_t h2a = i2 * P2;          uint32_t h2b = h2a + P2;
            uint32_t i0b = i0 + 1u;
            bool odd = (i0 & 1u) != 0u;

            const float2* __restrict__ tl  = g_tables + (l << 15);
            const float4* __restrict__ tl4 = (const float4*)tl;

            uint32_t idx0 = (i0  ^ h1a ^ h2a) & HASH_MASK;
            uint32_t idx1 = (i0b ^ h1a ^ h2a) & HASH_MASK;
            uint32_t idx2 = (i0  ^ h1b ^ h2a) & HASH_MASK;
            uint32_t idx3 = (i0b ^ h1b ^ h2a) & HASH_MASK;
            uint32_t idx4 = (i0  ^ h1a ^ h2b) & HASH_MASK;
            uint32_t idx5 = (i0b ^ h1a ^ h2b) & HASH_MASK;
            uint32_t idx6 = (i0  ^ h1b ^ h2b) & HASH_MASK;
            uint32_t idx7 = (i0b ^ h1b ^ h2b) & HASH_MASK;

            float4 q0 = __ldg(tl4 + (idx0 >> 1));
            float4 q2 = __ldg(tl4 + (idx2 >> 1));
            float4 q4 = __ldg(tl4 + (idx4 >> 1));
            float4 q6 = __ldg(tl4 + (idx6 >> 1));

            float2 s1 = make_float2(0.f, 0.f), s3 = s1, s5 = s1, s7 = s1;
            if (odd) {
                s1 = __ldg(tl + idx1);
                s3 = __ldg(tl + idx3);
                s5 = __ldg(tl + idx5);
                s7 = __ldg(tl + idx7);
            }

            bool hi0 = (idx0 & 1u) != 0u;
            bool hi2 = (idx2 & 1u) != 0u;
            bool hi4 = (idx4 & 1u) != 0u;
            bool hi6 = (idx6 & 1u) != 0u;

            float2 t0 = hi0 ? make_float2(q0.z, q0.w) : make_float2(q0.x, q0.y);
            float2 t2 = hi2 ? make_float2(q2.z, q2.w) : make_float2(q2.x, q2.y);
            float2 t4 = hi4 ? make_float2(q4.z, q4.w) : make_float2(q4.x, q4.y);
            float2 t6 = hi6 ? make_float2(q6.z, q6.w) : make_float2(q6.x, q6.y);

            float2 t1 = odd ? s1 : (hi0 ? make_float2(q0.x, q0.y) : make_float2(q0.z, q0.w));
            float2 t3 = odd ? s3 : (hi2 ? make_float2(q2.x, q2.y) : make_float2(q2.z, q2.w));
            float2 t5 = odd ? s5 : (hi4 ? make_float2(q4.x, q4.y) : make_float2(q4.z, q4.w));
            float2 t7 = odd ? s7 : (hi6 ? make_float2(q6.x, q6.y) : make_float2(q6.z, q6.w));

            float wc0 = v0 * v1 * v2;
            float wc1 = w0 * v1 * v2;
            float wc2 = v0 * w1 * v2;
            float wc3 = w0 * w1 * v2;
            float wc4 = v0 * v1 * w2;
            float wc5 = w0 * v1 * w2;
            float wc6 = v0 * w1 * w2;
            float wc7 = w0 * w1 * w2;

            float a0 = t0.x * wc0, a1 = t0.y * wc0;
            a0 = fmaf(t1.x, wc1, a0); a1 = fmaf(t1.y, wc1, a1);
            a0 = fmaf(t2.x, wc2, a0); a1 = fmaf(t2.y, wc2, a1);
            a0 = fmaf(t3.x, wc3, a0); a1 = fmaf(t3.y, wc3, a1);
            a0 = fmaf(t4.x, wc4, a0); a1 = fmaf(t4.y, wc4, a1);
            a0 = fmaf(t5.x, wc5, a0); a1 = fmaf(t5.y, wc5, a1);
            a0 = fmaf(t6.x, wc6, a0); a1 = fmaf(t6.y, wc6, a1);
            a0 = fmaf(t7.x, wc7, a0); a1 = fmaf(t7.y, wc7, a1);

            acc[2 * u + 0] = a0;
            acc[2 * u + 1] = a1;
        }
        a4 = make_float4(acc[0], acc[1], acc[2], acc[3]);
    }

    so[j * 9 + w] = a4;
    __syncthreads();

    int r = threadIdx.x >> 3;
    int c = threadIdx.x & 7;
    int ir = pb + r;
    if (ir < n) {
        int o = sorig[r];
        ((float4*)(out + (size_t)o * (2 * N_LEVELS)))[c] = so[r * 9 + c];
    }
}

extern "C" void kernel_launch(void* const* d_in, const int* in_sizes, int n_in,
                              void* d_out, int out_size) {
    const float* x       = (const float*)d_in[0];   // [N, 3]
    const float* tableA  = (const float*)d_in[1];   // [16, 32768, 4]
    const float* tableB  = (const float*)d_in[2];   // [16, 4, 2]
    float* out           = (float*)d_out;           // [N, 32]
    int n = in_sizes[0] / 3;
    if (n > MAXN) n = MAXN;   // scratch capacity (dataset is 524288)

    ResArr res;
    {
        double b = exp((log(512.0) - log(16.0)) / (double)(N_LEVELS - 1));
        for (int l = 0; l < N_LEVELS; l++)
            res.r[l] = (float)floor(16.0 * pow(b, (double)l));
    }

    int tab_entries = N_LEVELS * (int)HASHMAP_SIZE;
    materialize_kernel<<<(tab_entries + 255) / 256, 256>>>(tableA, tableB);

    // Spatial counting sort: hist -> fused self-zeroing scan -> scatter(x2).
    hist_kernel<<<(n + 255) / 256, 256>>>(x, n);
    scanAB_kernel<<<SCAN_BLOCKS, 1024>>>();
    int half = (n + 1) / 2;
    scatter_kernel<<<(half + 255) / 256, 256>>>(x, n);

    float4* xs_ptr = nullptr;
    cudaGetSymbolAddress((void**)&xs_ptr, g_xs4);
    encode_kernel<<<(n + 31) / 32, 256>>>(xs_ptr, out, n, res);
}